// round 4
// baseline (speedup 1.0000x reference)
#include <cuda_runtime.h>
#include <cuda_bf16.h>
#include <cstdint>

// LRML: out[b] = -|| ue + rel - ie ||^2
// Layout: 8 lanes per batch row (octet), each lane owns 4 of D=32 dims
// via one float4 load per table. Reductions = 3 shfl_xor (offsets 1,2,4).
// One warp handles 4 rows. 4096 warps total -> ~2x occupancy vs 4-lane
// layout, to hide the random-gather DRAM latency.

#define D 32
#define M 10
#define ROWS_PER_WARP 4
#define WARPS_PER_BLOCK 8
#define THREADS (WARPS_PER_BLOCK * 32)
#define ROWS_PER_BLOCK (WARPS_PER_BLOCK * ROWS_PER_WARP)

__device__ __forceinline__ float oct_sum(float v) {
    v += __shfl_xor_sync(0xFFFFFFFFu, v, 1);
    v += __shfl_xor_sync(0xFFFFFFFFu, v, 2);
    v += __shfl_xor_sync(0xFFFFFFFFu, v, 4);
    return v;
}

__global__ __launch_bounds__(THREADS)
void lrml_kernel(const int* __restrict__ user_ids,
                 const int* __restrict__ item_ids,
                 const float* __restrict__ user_emb,
                 const float* __restrict__ item_emb,
                 const float* __restrict__ W_att,
                 const float* __restrict__ memory,
                 float* __restrict__ out,
                 int B)
{
    __shared__ float4 sW[M * 8];    // W_att rows as float4 (10 x 32 floats)
    __shared__ float4 sMem[M * 8];  // memory rows as float4

    for (int i = threadIdx.x; i < M * 8; i += THREADS) {
        sW[i]   = ((const float4*)W_att)[i];
        sMem[i] = ((const float4*)memory)[i];
    }
    __syncthreads();

    const int lane = threadIdx.x & 31;
    const int s8   = lane & 7;        // which 4-dim slice (0..7)
    const int r    = lane >> 3;       // row within warp (0..3)
    const int warp = threadIdx.x >> 5;
    const int row  = blockIdx.x * ROWS_PER_BLOCK + warp * ROWS_PER_WARP + r;
    if (row >= B) return;

    const int uid = __ldg(&user_ids[row]);
    const int iid = __ldg(&item_ids[row]);

    // Each lane: 4 contiguous floats of its row (one float4 per table).
    float4 u = __ldg((const float4*)(user_emb + (size_t)uid * D + s8 * 4));
    float4 i = __ldg((const float4*)(item_emb + (size_t)iid * D + s8 * 4));

    float ue[4] = {u.x, u.y, u.z, u.w};
    float ie[4] = {i.x, i.y, i.z, i.w};

    // max_norm=1 renorm
    float us = 0.f, is = 0.f;
    #pragma unroll
    for (int j = 0; j < 4; j++) { us = fmaf(ue[j], ue[j], us); is = fmaf(ie[j], ie[j], is); }
    us = oct_sum(us);
    is = oct_sum(is);
    const float un = sqrtf(us), in = sqrtf(is);
    const float uscale = (un > 1.0f) ? (1.0f / un) : 1.0f;
    const float iscale = (in > 1.0f) ? (1.0f / in) : 1.0f;
    #pragma unroll
    for (int j = 0; j < 4; j++) { ue[j] *= uscale; ie[j] *= iscale; }

    float joint[4];
    #pragma unroll
    for (int j = 0; j < 4; j++) joint[j] = ue[j] * ie[j];

    // scores[m] = joint . W_att[m], reduced over the octet
    float sc[M];
    #pragma unroll
    for (int m = 0; m < M; m++) {
        float4 w = sW[m * 8 + s8];
        float p = joint[0] * w.x;
        p = fmaf(joint[1], w.y, p);
        p = fmaf(joint[2], w.z, p);
        p = fmaf(joint[3], w.w, p);
        sc[m] = oct_sum(p);
    }

    // softmax over M=10 (all lanes of the octet hold identical sc[])
    float mx = sc[0];
    #pragma unroll
    for (int m = 1; m < M; m++) mx = fmaxf(mx, sc[m]);
    float denom = 0.0f;
    #pragma unroll
    for (int m = 0; m < M; m++) { sc[m] = __expf(sc[m] - mx); denom += sc[m]; }
    const float inv_denom = 1.0f / denom;
    #pragma unroll
    for (int m = 0; m < M; m++) sc[m] *= inv_denom;

    // rel[j] = sum_m sc[m] * memory[m][s8*4+j]  (no reductions needed)
    float rel[4] = {0, 0, 0, 0};
    #pragma unroll
    for (int m = 0; m < M; m++) {
        float4 mm = sMem[m * 8 + s8];
        rel[0] = fmaf(sc[m], mm.x, rel[0]);
        rel[1] = fmaf(sc[m], mm.y, rel[1]);
        rel[2] = fmaf(sc[m], mm.z, rel[2]);
        rel[3] = fmaf(sc[m], mm.w, rel[3]);
    }

    float dist = 0.0f;
    #pragma unroll
    for (int j = 0; j < 4; j++) {
        const float diff = ue[j] + rel[j] - ie[j];
        dist = fmaf(diff, diff, dist);
    }
    dist = oct_sum(dist);

    if (s8 == 0) out[row] = -dist;
}

extern "C" void kernel_launch(void* const* d_in, const int* in_sizes, int n_in,
                              void* d_out, int out_size)
{
    const int*   user_ids = (const int*)  d_in[0];
    const int*   item_ids = (const int*)  d_in[1];
    const float* user_emb = (const float*)d_in[2];
    const float* item_emb = (const float*)d_in[3];
    const float* W_att    = (const float*)d_in[4];
    const float* memory   = (const float*)d_in[5];
    float*       out      = (float*)d_out;

    const int B = in_sizes[0];
    const int grid = (B + ROWS_PER_BLOCK - 1) / ROWS_PER_BLOCK;
    lrml_kernel<<<grid, THREADS>>>(user_ids, item_ids, user_emb, item_emb,
                                   W_att, memory, out, B);
}